// round 8
// baseline (speedup 1.0000x reference)
#include <cuda_runtime.h>
#include <cuda_fp16.h>
#include <cstdint>

// Problem constants
constexpr int NN = 100000;   // nodes
constexpr int NE = 1600000;  // edges
constexpr int NF = 128;      // input feats
constexpr int NC = 40;       // classes (post-projection feature width)

// ---------------- scratch (static device globals; no allocation) -------------
__device__ __align__(256) float  d_deg[NN];
__device__ __align__(256) float  d_invdeg[NN];
__device__ __align__(256) int    d_cnt[NN];
__device__ __align__(256) int    d_off[NN];
__device__ __align__(256) int    d_cur[NN];
__device__ int d_base;
__device__ __align__(256) int2   d_edat[NE];   // (row, w-as-bits), CSR by col
__device__ __align__(256) __half d_hA[(size_t)NN * NC];   // fp16 intermediates
__device__ __align__(256) __half d_hB[(size_t)NN * NC];

// ---------------- kernels ----------------------------------------------------

__global__ void zero2_kernel() {
    int i = blockIdx.x * blockDim.x + threadIdx.x;
    if (i < NN) { d_deg[i] = 0.0f; d_cnt[i] = 0; }
    if (i == 0) d_base = 0;
}

// deg[col] += ew and cnt[col] += 1 (guarded)
__global__ void degcnt_kernel(const int* __restrict__ row,
                              const int* __restrict__ col,
                              const float* __restrict__ ew) {
    int e = blockIdx.x * blockDim.x + threadIdx.x;
    if (e < NE) {
        int r = row[e];
        int c = col[e];
        if (c >= 0 && c < NN) {
            atomicAdd(&d_deg[c], ew[e]);
            if (r >= 0 && r < NN) atomicAdd(&d_cnt[c], 1);
        }
    }
}

// invdeg = 1/deg fused with decoupled block scan of cnt -> off/cur.
__global__ void scan_inv_kernel() {
    __shared__ int swarp[8];
    __shared__ int sbase;
    int t = threadIdx.x;
    int i = blockIdx.x * 256 + t;
    int v = 0;
    if (i < NN) {
        v = d_cnt[i];
        float d = d_deg[i];
        d_invdeg[i] = (d > 0.0f) ? (1.0f / d) : 0.0f;
    }

    int incl = v;
    #pragma unroll
    for (int o = 1; o < 32; o <<= 1) {
        int n = __shfl_up_sync(0xffffffffu, incl, o);
        if ((t & 31) >= o) incl += n;
    }
    if ((t & 31) == 31) swarp[t >> 5] = incl;
    __syncthreads();
    if (t < 8) {
        int w = swarp[t];
        #pragma unroll
        for (int o = 1; o < 8; o <<= 1) {
            int n = __shfl_up_sync(0xffu, w, o);
            if (t >= o) w += n;
        }
        swarp[t] = w;
    }
    __syncthreads();
    int blockIncl = incl + ((t >= 32) ? swarp[(t >> 5) - 1] : 0);
    if (t == 255) sbase = atomicAdd(&d_base, blockIncl);
    __syncthreads();
    if (i < NN) {
        int off = sbase + blockIncl - v;
        d_off[i] = off;
        d_cur[i] = off;
    }
}

// CSR fill: scaled weight w = ew * invdeg[row]  (ONE random gather per edge).
__global__ void fill_kernel(const int* __restrict__ row,
                            const int* __restrict__ col,
                            const float* __restrict__ ew) {
    int e = blockIdx.x * blockDim.x + threadIdx.x;
    if (e < NE) {
        int r = row[e];
        int c = col[e];
        if (r >= 0 && r < NN && c >= 0 && c < NN) {
            float w = ew[e] * d_invdeg[r];
            int pos = atomicAdd(&d_cur[c], 1);
            d_edat[pos] = make_int2(r, __float_as_int(w));
        }
    }
}

// y[NN,40] = fp16( sqrt(deg) * (x[NN,128] @ W[128,40]) )   -- prescale fused
__global__ void xw_kernel(const float* __restrict__ x,
                          const float* __restrict__ W,
                          __half* __restrict__ y) {
    __shared__ float sW[NF * NC];   // 20 KB
    __shared__ float sh[32][65];    // 8.3 KB (padded)
    int t = threadIdx.x;
    int nb = blockIdx.x * 64;

    for (int i = t; i < NF * NC; i += 128) sW[i] = W[i];

    int ng = t & 15;
    int cg = t >> 4;
    float acc[4][5] = {};

    for (int kc = 0; kc < NF; kc += 32) {
        __syncthreads();
        for (int i = t; i < 64 * 32; i += 128) {
            int n = i >> 5, k = i & 31;
            int node = nb + n;
            sh[k][n] = (node < NN) ? x[(size_t)node * NF + kc + k] : 0.0f;
        }
        __syncthreads();
        #pragma unroll 8
        for (int k = 0; k < 32; k++) {
            float hv[4], wv[5];
            #pragma unroll
            for (int i = 0; i < 4; i++) hv[i] = sh[k][ng * 4 + i];
            #pragma unroll
            for (int j = 0; j < 5; j++) wv[j] = sW[(kc + k) * NC + cg * 5 + j];
            #pragma unroll
            for (int i = 0; i < 4; i++)
                #pragma unroll
                for (int j = 0; j < 5; j++)
                    acc[i][j] += hv[i] * wv[j];
        }
    }
    #pragma unroll
    for (int i = 0; i < 4; i++) {
        int node = nb + ng * 4 + i;
        if (node < NN) {
            float sd = sqrtf(d_deg[node]);   // prescale: h'0 = D^{1/2} (xW)
            #pragma unroll
            for (int j = 0; j < 5; j++)
                y[(size_t)node * NC + cg * 5 + j] = __float2half(acc[i][j] * sd);
        }
    }
}

// Warp-per-node pull hop, fp16 -> fp16. 6 edge-groups x 5 lanes per warp:
// each iteration gathers 6 edges in parallel; shfl-reduce across groups at end.
__global__ void hop_h2h(const __half* __restrict__ hin,
                        __half* __restrict__ hout) {
    int node = (blockIdx.x * blockDim.x + threadIdx.x) >> 5;
    if (node >= NN) return;          // whole warp exits together
    int lane = threadIdx.x & 31;
    int g = lane / 5;                // 0..5 real groups; 6 for lanes 30,31
    int sub = lane - g * 5;

    int s = d_off[node];
    int e = d_cur[node];

    float acc[8] = {};
    if (g < 6) {
        int i = s + g;
        for (; i + 6 < e; i += 12) {
            int2 e0 = d_edat[i];
            int2 e1 = d_edat[i + 6];
            float w0 = __int_as_float(e0.y);
            float w1 = __int_as_float(e1.y);
            uint4 v0 = __ldg(reinterpret_cast<const uint4*>(hin + (size_t)e0.x * NC) + sub);
            uint4 v1 = __ldg(reinterpret_cast<const uint4*>(hin + (size_t)e1.x * NC) + sub);
            const unsigned* p0 = &v0.x;
            const unsigned* p1 = &v1.x;
            #pragma unroll
            for (int q = 0; q < 4; q++) {
                float2 f0 = __half22float2(*reinterpret_cast<const __half2*>(&p0[q]));
                float2 f1 = __half22float2(*reinterpret_cast<const __half2*>(&p1[q]));
                acc[2*q]   += f0.x * w0 + f1.x * w1;
                acc[2*q+1] += f0.y * w0 + f1.y * w1;
            }
        }
        if (i < e) {
            int2 e0 = d_edat[i];
            float w0 = __int_as_float(e0.y);
            uint4 v0 = __ldg(reinterpret_cast<const uint4*>(hin + (size_t)e0.x * NC) + sub);
            const unsigned* p0 = &v0.x;
            #pragma unroll
            for (int q = 0; q < 4; q++) {
                float2 f0 = __half22float2(*reinterpret_cast<const __half2*>(&p0[q]));
                acc[2*q]   += f0.x * w0;
                acc[2*q+1] += f0.y * w0;
            }
        }
    }
    // cross-group reduction: lanes 0-4 sum groups 1..5 (sources lanes 5..29, all valid)
    #pragma unroll
    for (int k = 0; k < 8; k++) {
        float t = acc[k];
        #pragma unroll
        for (int g2 = 1; g2 < 6; g2++)
            t += __shfl_sync(0xffffffffu, acc[k], (lane + 5 * g2) & 31);
        acc[k] = t;
    }
    if (lane < 5) {
        uint4 o;
        unsigned* po = &o.x;
        #pragma unroll
        for (int q = 0; q < 4; q++) {
            __half2 h = __floats2half2_rn(acc[2*q], acc[2*q+1]);
            po[q] = *reinterpret_cast<unsigned*>(&h);
        }
        *(reinterpret_cast<uint4*>(hout + (size_t)node * NC) + lane) = o;
    }
}

// Final hop, fp16 -> fp32 d_out, postscaled by dis = rsqrt(deg).
__global__ void hop_h2f(const __half* __restrict__ hin,
                        float* __restrict__ hout) {
    int node = (blockIdx.x * blockDim.x + threadIdx.x) >> 5;
    if (node >= NN) return;
    int lane = threadIdx.x & 31;
    int g = lane / 5;
    int sub = lane - g * 5;

    int s = d_off[node];
    int e = d_cur[node];

    float acc[8] = {};
    if (g < 6) {
        int i = s + g;
        for (; i + 6 < e; i += 12) {
            int2 e0 = d_edat[i];
            int2 e1 = d_edat[i + 6];
            float w0 = __int_as_float(e0.y);
            float w1 = __int_as_float(e1.y);
            uint4 v0 = __ldg(reinterpret_cast<const uint4*>(hin + (size_t)e0.x * NC) + sub);
            uint4 v1 = __ldg(reinterpret_cast<const uint4*>(hin + (size_t)e1.x * NC) + sub);
            const unsigned* p0 = &v0.x;
            const unsigned* p1 = &v1.x;
            #pragma unroll
            for (int q = 0; q < 4; q++) {
                float2 f0 = __half22float2(*reinterpret_cast<const __half2*>(&p0[q]));
                float2 f1 = __half22float2(*reinterpret_cast<const __half2*>(&p1[q]));
                acc[2*q]   += f0.x * w0 + f1.x * w1;
                acc[2*q+1] += f0.y * w0 + f1.y * w1;
            }
        }
        if (i < e) {
            int2 e0 = d_edat[i];
            float w0 = __int_as_float(e0.y);
            uint4 v0 = __ldg(reinterpret_cast<const uint4*>(hin + (size_t)e0.x * NC) + sub);
            const unsigned* p0 = &v0.x;
            #pragma unroll
            for (int q = 0; q < 4; q++) {
                float2 f0 = __half22float2(*reinterpret_cast<const __half2*>(&p0[q]));
                acc[2*q]   += f0.x * w0;
                acc[2*q+1] += f0.y * w0;
            }
        }
    }
    #pragma unroll
    for (int k = 0; k < 8; k++) {
        float t = acc[k];
        #pragma unroll
        for (int g2 = 1; g2 < 6; g2++)
            t += __shfl_sync(0xffffffffu, acc[k], (lane + 5 * g2) & 31);
        acc[k] = t;
    }
    if (lane < 5) {
        float dg = d_deg[node];
        float dis = (dg > 0.0f) ? rsqrtf(dg) : 0.0f;   // postscale h3 = D^{-1/2} h'3
        float4* dst = reinterpret_cast<float4*>(hout + (size_t)node * NC + lane * 8);
        dst[0] = make_float4(acc[0]*dis, acc[1]*dis, acc[2]*dis, acc[3]*dis);
        dst[1] = make_float4(acc[4]*dis, acc[5]*dis, acc[6]*dis, acc[7]*dis);
    }
}

// ---------------- launch ------------------------------------------------------

extern "C" void kernel_launch(void* const* d_in, const int* in_sizes, int n_in,
                              void* d_out, int out_size) {
    // Resolve inputs BY ELEMENT COUNT (order-independent; all counts distinct)
    const float* x  = nullptr;
    const int*   ei = nullptr;
    const float* ew = nullptr;
    const float* W  = nullptr;
    for (int i = 0; i < n_in; i++) {
        long long sz = in_sizes[i];
        if      (sz == (long long)NN * NF) x  = (const float*)d_in[i];
        else if (sz == (long long)2 * NE)  ei = (const int*)d_in[i];
        else if (sz == (long long)NE)      ew = (const float*)d_in[i];
        else if (sz == (long long)NF * NC) W  = (const float*)d_in[i];
    }
    float* out = (float*)d_out;

    const int* row = ei;        // edge_index[0, :]
    const int* col = ei + NE;   // edge_index[1, :]

    __half* hA; cudaGetSymbolAddress((void**)&hA, d_hA);
    __half* hB; cudaGetSymbolAddress((void**)&hB, d_hB);

    // --- prep: degrees, CSR by destination (invdeg fused into scan) ---
    zero2_kernel<<<(NN + 255)/256, 256>>>();
    degcnt_kernel<<<(NE + 255)/256, 256>>>(row, col, ew);
    scan_inv_kernel<<<(NN + 255)/256, 256>>>();
    fill_kernel<<<(NE + 255)/256, 256>>>(row, col, ew);

    // --- project first + prescale: hA = fp16(sqrt(deg) * (x @ W)) ---
    xw_kernel<<<(NN + 63)/64, 128>>>(x, W, hA);

    // --- three pull-mode hops (warp per node; fp32 accum, fp16 intermediates) ---
    const int HOP_BLOCKS = (NN * 32 + 255) / 256;   // one warp per node
    hop_h2h<<<HOP_BLOCKS, 256>>>(hA, hB);
    hop_h2h<<<HOP_BLOCKS, 256>>>(hB, hA);
    hop_h2f<<<HOP_BLOCKS, 256>>>(hA, out);
}

// round 9
// speedup vs baseline: 1.3254x; 1.3254x over previous
#include <cuda_runtime.h>
#include <cuda_fp16.h>
#include <cstdint>

// Problem constants
constexpr int NN = 100000;   // nodes
constexpr int NE = 1600000;  // edges
constexpr int NF = 128;      // input feats
constexpr int NC = 40;       // classes (post-projection feature width)

// ---------------- scratch (static device globals; no allocation) -------------
__device__ __align__(256) float2 d_dc[NN];      // (weighted deg, edge count)
__device__ __align__(256) float  d_invdeg[NN];
__device__ __align__(256) int    d_off[NN];
__device__ __align__(256) int    d_cur[NN];
__device__ int d_base;
__device__ __align__(256) int2   d_edat[NE];    // (row, w-as-bits), CSR by col
__device__ __align__(256) __half d_hA[(size_t)NN * NC];   // fp16 intermediates
__device__ __align__(256) __half d_hB[(size_t)NN * NC];

// ---------------- kernels ----------------------------------------------------

__global__ void zero2_kernel() {
    int i = blockIdx.x * blockDim.x + threadIdx.x;
    if (i < NN) d_dc[i] = make_float2(0.f, 0.f);
    if (i == 0) d_base = 0;
}

// one vector reduction per edge: {deg += ew, cnt += 1}
__global__ void degcnt_kernel(const int* __restrict__ row,
                              const int* __restrict__ col,
                              const float* __restrict__ ew) {
    int e = blockIdx.x * blockDim.x + threadIdx.x;
    if (e < NE) {
        int r = row[e];
        int c = col[e];
        if (c >= 0 && c < NN && r >= 0 && r < NN) {
            float w = ew[e];
            asm volatile("red.global.add.v2.f32 [%0], {%1,%2};"
                         :: "l"(&d_dc[c]), "f"(w), "f"(1.0f) : "memory");
        }
    }
}

// invdeg = 1/deg fused with decoupled block scan of cnt -> off/cur.
// Offsets are NOT node-ordered (block bases from one atomic) — fine for pull.
__global__ void scan_inv_kernel() {
    __shared__ int swarp[8];
    __shared__ int sbase;
    int t = threadIdx.x;
    int i = blockIdx.x * 256 + t;
    int v = 0;
    if (i < NN) {
        float2 dc = d_dc[i];
        v = (int)(dc.y + 0.5f);
        d_invdeg[i] = (dc.x > 0.0f) ? (1.0f / dc.x) : 0.0f;
    }

    int incl = v;
    #pragma unroll
    for (int o = 1; o < 32; o <<= 1) {
        int n = __shfl_up_sync(0xffffffffu, incl, o);
        if ((t & 31) >= o) incl += n;
    }
    if ((t & 31) == 31) swarp[t >> 5] = incl;
    __syncthreads();
    if (t < 8) {
        int w = swarp[t];
        #pragma unroll
        for (int o = 1; o < 8; o <<= 1) {
            int n = __shfl_up_sync(0xffu, w, o);
            if (t >= o) w += n;
        }
        swarp[t] = w;
    }
    __syncthreads();
    int blockIncl = incl + ((t >= 32) ? swarp[(t >> 5) - 1] : 0);
    if (t == 255) sbase = atomicAdd(&d_base, blockIncl);
    __syncthreads();
    if (i < NN) {
        int off = sbase + blockIncl - v;
        d_off[i] = off;
        d_cur[i] = off;
    }
}

// CSR fill: scaled weight w = ew * invdeg[row]  (ONE random gather per edge).
__global__ void fill_kernel(const int* __restrict__ row,
                            const int* __restrict__ col,
                            const float* __restrict__ ew) {
    int e = blockIdx.x * blockDim.x + threadIdx.x;
    if (e < NE) {
        int r = row[e];
        int c = col[e];
        if (r >= 0 && r < NN && c >= 0 && c < NN) {
            float w = ew[e] * d_invdeg[r];
            int pos = atomicAdd(&d_cur[c], 1);
            d_edat[pos] = make_int2(r, __float_as_int(w));
        }
    }
}

// y[NN,40] = fp16( sqrt(deg) * (x[NN,128] @ W[128,40]) )   -- prescale fused
__global__ void xw_kernel(const float* __restrict__ x,
                          const float* __restrict__ W,
                          __half* __restrict__ y) {
    __shared__ float sW[NF * NC];   // 20 KB
    __shared__ float sh[32][65];    // 8.3 KB (padded)
    int t = threadIdx.x;
    int nb = blockIdx.x * 64;

    for (int i = t; i < NF * NC; i += 128) sW[i] = W[i];

    int ng = t & 15;
    int cg = t >> 4;
    float acc[4][5] = {};

    for (int kc = 0; kc < NF; kc += 32) {
        __syncthreads();
        for (int i = t; i < 64 * 32; i += 128) {
            int n = i >> 5, k = i & 31;
            int node = nb + n;
            sh[k][n] = (node < NN) ? x[(size_t)node * NF + kc + k] : 0.0f;
        }
        __syncthreads();
        #pragma unroll 8
        for (int k = 0; k < 32; k++) {
            float hv[4], wv[5];
            #pragma unroll
            for (int i = 0; i < 4; i++) hv[i] = sh[k][ng * 4 + i];
            #pragma unroll
            for (int j = 0; j < 5; j++) wv[j] = sW[(kc + k) * NC + cg * 5 + j];
            #pragma unroll
            for (int i = 0; i < 4; i++)
                #pragma unroll
                for (int j = 0; j < 5; j++)
                    acc[i][j] += hv[i] * wv[j];
        }
    }
    #pragma unroll
    for (int i = 0; i < 4; i++) {
        int node = nb + ng * 4 + i;
        if (node < NN) {
            float sd = sqrtf(d_dc[node].x);   // prescale: h'0 = D^{1/2}(xW)
            #pragma unroll
            for (int j = 0; j < 5; j++)
                y[(size_t)node * NC + cg * 5 + j] = __float2half(acc[i][j] * sd);
        }
    }
}

// Pull hop, fp16 -> fp16. 5-lane group per node (row = 40 halves = 5 uint4),
// 6 nodes/warp. fp32 accumulation, unroll-4 gather for MLP. No atomics.
__global__ void hop_h2h(const __half* __restrict__ hin,
                        __half* __restrict__ hout) {
    int gwarp = (blockIdx.x * blockDim.x + threadIdx.x) >> 5;
    int ln = threadIdx.x & 31;
    if (ln >= 30) return;
    int node = gwarp * 6 + ln / 5;
    if (node >= NN) return;
    int sub = ln % 5;

    int s = d_off[node];
    int e = d_cur[node];

    float acc[8] = {};
    int i = s;
    for (; i + 4 <= e; i += 4) {
        int2 ed[4];
        uint4 v[4];
        #pragma unroll
        for (int u = 0; u < 4; u++) ed[u] = d_edat[i + u];
        #pragma unroll
        for (int u = 0; u < 4; u++)
            v[u] = __ldg(reinterpret_cast<const uint4*>(hin + (size_t)ed[u].x * NC) + sub);
        #pragma unroll
        for (int u = 0; u < 4; u++) {
            float w = __int_as_float(ed[u].y);
            const unsigned* p = &v[u].x;
            #pragma unroll
            for (int q = 0; q < 4; q++) {
                float2 f = __half22float2(*reinterpret_cast<const __half2*>(&p[q]));
                acc[2*q]   += f.x * w;
                acc[2*q+1] += f.y * w;
            }
        }
    }
    for (; i < e; i++) {
        int2 e0 = d_edat[i];
        float w = __int_as_float(e0.y);
        uint4 v0 = __ldg(reinterpret_cast<const uint4*>(hin + (size_t)e0.x * NC) + sub);
        const unsigned* p = &v0.x;
        #pragma unroll
        for (int q = 0; q < 4; q++) {
            float2 f = __half22float2(*reinterpret_cast<const __half2*>(&p[q]));
            acc[2*q]   += f.x * w;
            acc[2*q+1] += f.y * w;
        }
    }
    uint4 o;
    unsigned* po = &o.x;
    #pragma unroll
    for (int q = 0; q < 4; q++) {
        __half2 h = __floats2half2_rn(acc[2*q], acc[2*q+1]);
        po[q] = *reinterpret_cast<unsigned*>(&h);
    }
    *(reinterpret_cast<uint4*>(hout + (size_t)node * NC) + sub) = o;
}

// Final hop, fp16 -> fp32 d_out, postscaled by rsqrt(deg).
__global__ void hop_h2f(const __half* __restrict__ hin,
                        float* __restrict__ hout) {
    int gwarp = (blockIdx.x * blockDim.x + threadIdx.x) >> 5;
    int ln = threadIdx.x & 31;
    if (ln >= 30) return;
    int node = gwarp * 6 + ln / 5;
    if (node >= NN) return;
    int sub = ln % 5;

    int s = d_off[node];
    int e = d_cur[node];

    float acc[8] = {};
    int i = s;
    for (; i + 4 <= e; i += 4) {
        int2 ed[4];
        uint4 v[4];
        #pragma unroll
        for (int u = 0; u < 4; u++) ed[u] = d_edat[i + u];
        #pragma unroll
        for (int u = 0; u < 4; u++)
            v[u] = __ldg(reinterpret_cast<const uint4*>(hin + (size_t)ed[u].x * NC) + sub);
        #pragma unroll
        for (int u = 0; u < 4; u++) {
            float w = __int_as_float(ed[u].y);
            const unsigned* p = &v[u].x;
            #pragma unroll
            for (int q = 0; q < 4; q++) {
                float2 f = __half22float2(*reinterpret_cast<const __half2*>(&p[q]));
                acc[2*q]   += f.x * w;
                acc[2*q+1] += f.y * w;
            }
        }
    }
    for (; i < e; i++) {
        int2 e0 = d_edat[i];
        float w = __int_as_float(e0.y);
        uint4 v0 = __ldg(reinterpret_cast<const uint4*>(hin + (size_t)e0.x * NC) + sub);
        const unsigned* p = &v0.x;
        #pragma unroll
        for (int q = 0; q < 4; q++) {
            float2 f = __half22float2(*reinterpret_cast<const __half2*>(&p[q]));
            acc[2*q]   += f.x * w;
            acc[2*q+1] += f.y * w;
        }
    }
    float dg = d_dc[node].x;
    float dis = (dg > 0.0f) ? rsqrtf(dg) : 0.0f;   // postscale h3 = D^{-1/2} h'3
    float4* dst = reinterpret_cast<float4*>(hout + (size_t)node * NC + sub * 8);
    dst[0] = make_float4(acc[0]*dis, acc[1]*dis, acc[2]*dis, acc[3]*dis);
    dst[1] = make_float4(acc[4]*dis, acc[5]*dis, acc[6]*dis, acc[7]*dis);
}

// ---------------- launch ------------------------------------------------------

extern "C" void kernel_launch(void* const* d_in, const int* in_sizes, int n_in,
                              void* d_out, int out_size) {
    // Resolve inputs BY ELEMENT COUNT (order-independent; all counts distinct)
    const float* x  = nullptr;
    const int*   ei = nullptr;
    const float* ew = nullptr;
    const float* W  = nullptr;
    for (int i = 0; i < n_in; i++) {
        long long sz = in_sizes[i];
        if      (sz == (long long)NN * NF) x  = (const float*)d_in[i];
        else if (sz == (long long)2 * NE)  ei = (const int*)d_in[i];
        else if (sz == (long long)NE)      ew = (const float*)d_in[i];
        else if (sz == (long long)NF * NC) W  = (const float*)d_in[i];
    }
    float* out = (float*)d_out;

    const int* row = ei;        // edge_index[0, :]
    const int* col = ei + NE;   // edge_index[1, :]

    __half* hA; cudaGetSymbolAddress((void**)&hA, d_hA);
    __half* hB; cudaGetSymbolAddress((void**)&hB, d_hB);

    // --- prep: degrees, CSR by destination (invdeg fused into scan) ---
    zero2_kernel<<<(NN + 255)/256, 256>>>();
    degcnt_kernel<<<(NE + 255)/256, 256>>>(row, col, ew);
    scan_inv_kernel<<<(NN + 255)/256, 256>>>();
    fill_kernel<<<(NE + 255)/256, 256>>>(row, col, ew);

    // --- project first + prescale: hA = fp16(sqrt(deg) * (x @ W)) ---
    xw_kernel<<<(NN + 63)/64, 128>>>(x, W, hA);

    // --- three pull-mode hops (6 nodes/warp, 5-lane groups; fp32 accum) ---
    const int WARPS = (NN + 5) / 6;
    const int HOP_BLOCKS = (WARPS * 32 + 255) / 256;
    hop_h2h<<<HOP_BLOCKS, 256>>>(hA, hB);
    hop_h2h<<<HOP_BLOCKS, 256>>>(hB, hA);
    hop_h2f<<<HOP_BLOCKS, 256>>>(hA, out);
}